// round 14
// baseline (speedup 1.0000x reference)
#include <cuda_runtime.h>
#include <cuda_fp16.h>
#include <mma.h>
#include <cstdint>

using namespace nvcuda;

#define N_NODES 100000
#define N_EDGES 1600000
#define F_IN    128
#define F_HID   64
#define F_OUT   40

#define SCAN_T  1024
#define SCAN_NB ((N_NODES + SCAN_T - 1) / SCAN_T)   // 98

// ---------------- scratch (static device globals; no allocation) ----------------
__device__ int    g_degs_i[N_NODES];
__device__ int    g_degd_i[N_NODES];
__device__ float  g_nd[N_NODES];
__device__ int    g_incl[N_NODES];
__device__ int    g_rowoff[N_NODES + 1];
__device__ int    g_partial[SCAN_NB];
__device__ int    g_pos[N_EDGES];
__device__ int    g_csrc[N_EDGES];
__device__ __half g_hh   [(size_t)N_NODES * F_IN];
__device__ __half g_xw64 [(size_t)N_NODES * F_HID];   // gemm0 output
__device__ __half g_xw64b[(size_t)N_NODES * F_HID];   // fused layer-1 output
__device__ __half g_xw40 [(size_t)N_NODES * F_OUT];   // fused layer-2 output

// inline ns from src-degree
__device__ __forceinline__ float ns_of(int node) {
    return rsqrtf(fmaxf((float)g_degs_i[node], 1.0f));
}

// ---------------- h -> fp16 streaming convert ----------------
__global__ void k_cvt_h(const float* __restrict__ h) {
    int i = blockIdx.x * blockDim.x + threadIdx.x;
    if (i < N_NODES * F_IN / 8) {
        const float4 a = __ldg(&((const float4*)h)[2 * i + 0]);
        const float4 b = __ldg(&((const float4*)h)[2 * i + 1]);
        union { uint4 u; __half2 x[4]; } o;
        o.x[0] = __floats2half2_rn(a.x, a.y);
        o.x[1] = __floats2half2_rn(a.z, a.w);
        o.x[2] = __floats2half2_rn(b.x, b.y);
        o.x[3] = __floats2half2_rn(b.z, b.w);
        ((uint4*)g_hh)[i] = o.u;
    }
}

// ---------------- per-stream degree zeroing ----------------
__global__ void k_zero_degd() {
    int i = blockIdx.x * blockDim.x + threadIdx.x;
    if (i < N_NODES / 4) ((int4*)g_degd_i)[i] = make_int4(0, 0, 0, 0);
}
__global__ void k_zero_degs() {
    int i = blockIdx.x * blockDim.x + threadIdx.x;
    if (i < N_NODES / 4) ((int4*)g_degs_i)[i] = make_int4(0, 0, 0, 0);
}

// ---------------- dst histogram + per-edge position capture ----------------
__global__ void k_deg_dst_pos(const int* __restrict__ dst) {
    int i = blockIdx.x * blockDim.x + threadIdx.x;
    if (i < N_EDGES / 4) {
        const int4 d = __ldg(&((const int4*)dst)[i]);
        int4 p;
        p.x = atomicAdd(&g_degd_i[d.x], 1);
        p.y = atomicAdd(&g_degd_i[d.y], 1);
        p.z = atomicAdd(&g_degd_i[d.z], 1);
        p.w = atomicAdd(&g_degd_i[d.w], 1);
        ((int4*)g_pos)[i] = p;
    }
}

__global__ void k_deg_src(const int* __restrict__ src) {
    int i = blockIdx.x * blockDim.x + threadIdx.x;
    if (i < N_EDGES / 4) {
        const int4 s = __ldg(&((const int4*)src)[i]);
        atomicAdd(&g_degs_i[s.x], 1);
        atomicAdd(&g_degs_i[s.y], 1);
        atomicAdd(&g_degs_i[s.z], 1);
        atomicAdd(&g_degs_i[s.w], 1);
    }
}

// ---------------- CSR build ----------------
__global__ __launch_bounds__(SCAN_T) void k_scan_block() {
    __shared__ int ws[32];
    int g = blockIdx.x * SCAN_T + threadIdx.x;
    int lane = threadIdx.x & 31, wid = threadIdx.x >> 5;
    int x = (g < N_NODES) ? g_degd_i[g] : 0;
#pragma unroll
    for (int o = 1; o < 32; o <<= 1) {
        int y = __shfl_up_sync(0xFFFFFFFFu, x, o);
        if (lane >= o) x += y;
    }
    if (lane == 31) ws[wid] = x;
    __syncthreads();
    if (wid == 0) {
        int y = ws[lane];
#pragma unroll
        for (int o = 1; o < 32; o <<= 1) {
            int z = __shfl_up_sync(0xFFFFFFFFu, y, o);
            if (lane >= o) y += z;
        }
        ws[lane] = y;
    }
    __syncthreads();
    int incl = x + (wid > 0 ? ws[wid - 1] : 0);
    if (g < N_NODES) g_incl[g] = incl;
    if (threadIdx.x == SCAN_T - 1) g_partial[blockIdx.x] = incl;
}

__global__ __launch_bounds__(SCAN_T) void k_finalize() {
    __shared__ int ws[32];
    __shared__ int s_off;
    const int tid = threadIdx.x;
    const int lane = tid & 31, w = tid >> 5;

    int v = 0;
    if (tid < SCAN_NB && tid < blockIdx.x) v = g_partial[tid];
#pragma unroll
    for (int o = 16; o > 0; o >>= 1) v += __shfl_down_sync(0xFFFFFFFFu, v, o);
    if (tid < 128 && lane == 0) ws[w] = v;
    __syncthreads();
    if (tid == 0) s_off = ws[0] + ws[1] + ws[2] + ws[3];
    __syncthreads();
    const int off = s_off;

    int g = blockIdx.x * SCAN_T + tid;
    if (g < N_NODES) {
        int dd   = g_degd_i[g];
        int incl = g_incl[g] + off;
        g_rowoff[g + 1] = incl;
        if (g == 0) g_rowoff[0] = 0;
        g_nd[g] = rsqrtf(fmaxf((float)dd, 1.0f));
    }
}

__global__ void k_fill(const int* __restrict__ src, const int* __restrict__ dst) {
    int i = blockIdx.x * blockDim.x + threadIdx.x;
    if (i < N_EDGES / 4) {
        const int4 s = __ldg(&((const int4*)src)[i]);
        const int4 d = __ldg(&((const int4*)dst)[i]);
        const int4 p = __ldg(&((const int4*)g_pos)[i]);
        g_csrc[__ldg(&g_rowoff[d.x]) + p.x] = s.x;
        g_csrc[__ldg(&g_rowoff[d.y]) + p.y] = s.y;
        g_csrc[__ldg(&g_rowoff[d.z]) + p.z] = s.z;
        g_csrc[__ldg(&g_rowoff[d.w]) + p.w] = s.w;
    }
}

// ---------------- gemm0: HMMA, K=128 pipelined: Y = (hh @ W0) * ns -> fp16 ----------------
__global__ __launch_bounds__(256) void k_gemm0(const __half* __restrict__ X,
                                               const float* __restrict__ W,
                                               __half* __restrict__ Y) {
    static constexpr int K = F_IN, M = F_HID;
    static constexpr int KC = 64, NC = K / KC;
    static constexpr int AL = 72, BL = 72;
    static constexpr int A_HALVES = 128 * AL;
    static constexpr int AB_BYTES = 2 * A_HALVES * 2 + K * BL * 2;
    static constexpr int STAGE_BYTES = 8 * 16 * 64 * 4;
    static constexpr int SMEM_BYTES = AB_BYTES > STAGE_BYTES ? AB_BYTES : STAGE_BYTES;

    __shared__ __align__(16) char smem[SMEM_BYTES];
    __half* As0 = (__half*)smem;
    __half* As1 = (__half*)smem + A_HALVES;
    __half* Bs  = (__half*)smem + 2 * A_HALVES;
    float*  Cs  = (float*)smem;

    const int tid  = threadIdx.x;
    const int warp = tid >> 5;
    const int lane = tid & 31;
    const int row0 = blockIdx.x * 128;

    const int ar   = tid >> 1;
    const int ah   = (tid & 1) * 32;
    const int lrow = row0 + ar;
    const bool lok = (lrow < N_NODES);

#pragma unroll
    for (int i = 0; i < K / 16; i++) {
        const int q    = i * 256 + tid;
        const int brow = q >> 4;
        const int bcol = (q & 15) * 4;
        float4 wv = make_float4(0.f, 0.f, 0.f, 0.f);
        if (bcol < M)
            wv = *(const float4*)&W[(size_t)brow * M + bcol];
        union { uint2 u; __half2 h[2]; } p;
        p.h[0] = __floats2half2_rn(wv.x, wv.y);
        p.h[1] = __floats2half2_rn(wv.z, wv.w);
        *(uint2*)&Bs[brow * BL + bcol] = p.u;
    }

    uint4 raw[4] = {{0,0,0,0}, {0,0,0,0}, {0,0,0,0}, {0,0,0,0}};
    if (lok) {
#pragma unroll
        for (int u = 0; u < 4; u++)
            raw[u] = __ldg((const uint4*)&X[(size_t)lrow * K + ah + u * 8]);
    }
#pragma unroll
    for (int u = 0; u < 4; u++)
        *(uint4*)&As0[ar * AL + ah + u * 8] = raw[u];
    __syncthreads();

    wmma::fragment<wmma::accumulator, 16, 16, 16, float> cf[4];
#pragma unroll
    for (int n = 0; n < 4; n++) wmma::fill_fragment(cf[n], 0.0f);

#pragma unroll
    for (int c = 0; c < NC; c++) {
        if (c + 1 < NC && lok) {
#pragma unroll
            for (int u = 0; u < 4; u++)
                raw[u] = __ldg((const uint4*)&X[(size_t)lrow * K + (c + 1) * KC + ah + u * 8]);
        }
        const __half* Ac = (c & 1) ? As1 : As0;
#pragma unroll
        for (int kc = 0; kc < KC; kc += 16) {
            wmma::fragment<wmma::matrix_a, 16, 16, 16, __half, wmma::row_major> af;
            wmma::load_matrix_sync(af, &Ac[(warp * 16) * AL + kc], AL);
#pragma unroll
            for (int n = 0; n < 4; n++) {
                wmma::fragment<wmma::matrix_b, 16, 16, 16, __half, wmma::row_major> bf;
                wmma::load_matrix_sync(bf, &Bs[(c * KC + kc) * BL + n * 16], BL);
                wmma::mma_sync(cf[n], af, bf, cf[n]);
            }
        }
        if (c + 1 < NC) {
            __half* Ad = ((c + 1) & 1) ? As1 : As0;
#pragma unroll
            for (int u = 0; u < 4; u++)
                *(uint4*)&Ad[ar * AL + ah + u * 8] = raw[u];
            __syncthreads();
        }
    }
    __syncthreads();

    float* cwarp = Cs + warp * (16 * 64);
#pragma unroll
    for (int n = 0; n < 4; n++)
        wmma::store_matrix_sync(cwarp + n * 16, cf[n], 64, wmma::mem_row_major);
    __syncwarp();

    for (int q = lane; q < 256; q += 32) {
        const int r  = q >> 4;
        const int qc = (q & 15) * 4;
        const int rr = row0 + warp * 16 + r;
        if (rr < N_NODES && qc < M) {
            const float s = ns_of(rr);
            union { uint2 u; __half2 h[2]; } p;
            p.h[0] = __floats2half2_rn(cwarp[r * 64 + qc + 0] * s, cwarp[r * 64 + qc + 1] * s);
            p.h[1] = __floats2half2_rn(cwarp[r * 64 + qc + 2] * s, cwarp[r * 64 + qc + 3] * s);
            *(uint2*)&Y[(size_t)rr * M + qc] = p.u;
        }
    }
}

// ---------------- fused gather64 + GEMM (K=64): Y = (relu(gather(XW)*nd + b) @ W) * ns ----------------
// Block = 128 nodes, 256 threads. Gather: 2 threads/node, 32 feats each, fp32 accum.
// A-tile written to smem in fp16, then single-chunk HMMA.
template <int M>
__global__ __launch_bounds__(256) void k_fused(const __half* __restrict__ XW,
                                               const float* __restrict__ W,
                                               __half* __restrict__ Y,
                                               const float* __restrict__ bpre) {
    static constexpr int K = 64;
    static constexpr int AL = 72, BL = 72;
    static constexpr int A_HALVES = 128 * AL;
    static constexpr int AB_BYTES = A_HALVES * 2 + K * BL * 2;
    static constexpr int STAGE_BYTES = 8 * 16 * 64 * 4;
    static constexpr int SMEM_BYTES = AB_BYTES > STAGE_BYTES ? AB_BYTES : STAGE_BYTES;

    __shared__ __align__(16) char smem[SMEM_BYTES];
    __half* As = (__half*)smem;
    __half* Bs = (__half*)smem + A_HALVES;
    float*  Cs = (float*)smem;

    const int tid  = threadIdx.x;
    const int warp = tid >> 5;
    const int lane = tid & 31;
    const int row0 = blockIdx.x * 128;

    // ---- B load: 64 x M fp32 -> fp16 ----
#pragma unroll
    for (int i = 0; i < K / 16; i++) {
        const int q    = i * 256 + tid;
        const int brow = q >> 4;
        const int bcol = (q & 15) * 4;
        float4 wv = make_float4(0.f, 0.f, 0.f, 0.f);
        if (bcol < M)
            wv = *(const float4*)&W[(size_t)brow * M + bcol];
        union { uint2 u; __half2 h[2]; } p;
        p.h[0] = __floats2half2_rn(wv.x, wv.y);
        p.h[1] = __floats2half2_rn(wv.z, wv.w);
        *(uint2*)&Bs[brow * BL + bcol] = p.u;
    }

    // ---- gather phase: 2 threads/node, 32 feats each ----
    const int ar   = tid >> 1;
    const int fh   = (tid & 1) * 32;        // feature half offset
    const int node = row0 + ar;
    const bool ok  = (node < N_NODES);

    float acc[32];
#pragma unroll
    for (int j = 0; j < 32; j++) acc[j] = 0.0f;

    if (ok) {
        int       i   = g_rowoff[node];
        const int end = g_rowoff[node + 1];
        for (; i + 1 < end; i += 2) {
            const int s0 = __ldg(&g_csrc[i + 0]);
            const int s1 = __ldg(&g_csrc[i + 1]);
            uint4 r0[4], r1[4];
#pragma unroll
            for (int u = 0; u < 4; u++) {
                r0[u] = __ldg((const uint4*)&XW[(size_t)s0 * 64 + fh + u * 8]);
                r1[u] = __ldg((const uint4*)&XW[(size_t)s1 * 64 + fh + u * 8]);
            }
#pragma unroll
            for (int u = 0; u < 4; u++) {
                union { uint4 q; __half2 h[4]; } p0, p1;
                p0.q = r0[u]; p1.q = r1[u];
#pragma unroll
                for (int j = 0; j < 4; j++) {
                    const float2 v0 = __half22float2(p0.h[j]);
                    const float2 v1 = __half22float2(p1.h[j]);
                    acc[u * 8 + 2 * j + 0] += v0.x + v1.x;
                    acc[u * 8 + 2 * j + 1] += v0.y + v1.y;
                }
            }
        }
        for (; i < end; i++) {
            const int s = __ldg(&g_csrc[i]);
#pragma unroll
            for (int u = 0; u < 4; u++) {
                union { uint4 q; __half2 h[4]; } p;
                p.q = __ldg((const uint4*)&XW[(size_t)s * 64 + fh + u * 8]);
#pragma unroll
                for (int j = 0; j < 4; j++) {
                    const float2 v = __half22float2(p.h[j]);
                    acc[u * 8 + 2 * j + 0] += v.x;
                    acc[u * 8 + 2 * j + 1] += v.y;
                }
            }
        }
    }

    // PRE epilogue (fp32): x' = relu(acc * nd + b), convert fp16 -> As
    {
        const float ndv = ok ? g_nd[node] : 0.0f;
#pragma unroll
        for (int u = 0; u < 4; u++) {
            union { uint4 q; __half2 h[4]; } o;
#pragma unroll
            for (int j = 0; j < 4; j++) {
                const int k = fh + u * 8 + 2 * j;
                o.h[j] = __floats2half2_rn(
                    fmaxf(fmaf(acc[u * 8 + 2 * j + 0], ndv, __ldg(&bpre[k + 0])), 0.f),
                    fmaxf(fmaf(acc[u * 8 + 2 * j + 1], ndv, __ldg(&bpre[k + 1])), 0.f));
            }
            *(uint4*)&As[ar * AL + fh + u * 8] = o.q;
        }
    }
    __syncthreads();

    // ---- MMA: single K=64 chunk ----
    wmma::fragment<wmma::accumulator, 16, 16, 16, float> cf[4];
#pragma unroll
    for (int n = 0; n < 4; n++) wmma::fill_fragment(cf[n], 0.0f);

#pragma unroll
    for (int kc = 0; kc < K; kc += 16) {
        wmma::fragment<wmma::matrix_a, 16, 16, 16, __half, wmma::row_major> af;
        wmma::load_matrix_sync(af, &As[(warp * 16) * AL + kc], AL);
#pragma unroll
        for (int n = 0; n < 4; n++) {
            wmma::fragment<wmma::matrix_b, 16, 16, 16, __half, wmma::row_major> bf;
            wmma::load_matrix_sync(bf, &Bs[kc * BL + n * 16], BL);
            wmma::mma_sync(cf[n], af, bf, cf[n]);
        }
    }
    __syncthreads();   // As/Bs dead; reuse as staging

    float* cwarp = Cs + warp * (16 * 64);
#pragma unroll
    for (int n = 0; n < 4; n++)
        wmma::store_matrix_sync(cwarp + n * 16, cf[n], 64, wmma::mem_row_major);
    __syncwarp();

    for (int q = lane; q < 256; q += 32) {
        const int r  = q >> 4;
        const int qc = (q & 15) * 4;
        const int rr = row0 + warp * 16 + r;
        if (rr < N_NODES && qc < M) {
            const float s = ns_of(rr);
            union { uint2 u; __half2 h[2]; } p;
            p.h[0] = __floats2half2_rn(cwarp[r * 64 + qc + 0] * s, cwarp[r * 64 + qc + 1] * s);
            p.h[1] = __floats2half2_rn(cwarp[r * 64 + qc + 2] * s, cwarp[r * 64 + qc + 3] * s);
            *(uint2*)&Y[(size_t)rr * M + qc] = p.u;
        }
    }
}

// ---------------- 40-wide fp16 gather with fused final epilogue (fp32 output) ----------------
__device__ __forceinline__ void h4_acc(float4& acc, uint2 raw) {
    union { uint2 u; __half2 h[2]; } p; p.u = raw;
    const float2 a = __half22float2(p.h[0]);
    const float2 b = __half22float2(p.h[1]);
    acc.x += a.x; acc.y += a.y; acc.z += b.x; acc.w += b.y;
}

__global__ __launch_bounds__(256) void k_gather40(const __half* __restrict__ xw,
                                                  float* __restrict__ out,
                                                  const float* __restrict__ b2) {
    const int node = blockIdx.x * 16 + (threadIdx.x >> 4);
    if (node >= N_NODES) return;
    const int f = (threadIdx.x & 15) << 2;
    if (f >= F_OUT) return;
    int       i   = g_rowoff[node];
    const int end = g_rowoff[node + 1];
    float4 acc = make_float4(0.f, 0.f, 0.f, 0.f);
    for (; i + 3 < end; i += 4) {
        const int s0 = __ldg(&g_csrc[i + 0]);
        const int s1 = __ldg(&g_csrc[i + 1]);
        const int s2 = __ldg(&g_csrc[i + 2]);
        const int s3 = __ldg(&g_csrc[i + 3]);
        h4_acc(acc, __ldg((const uint2*)&xw[(size_t)s0 * F_OUT + f]));
        h4_acc(acc, __ldg((const uint2*)&xw[(size_t)s1 * F_OUT + f]));
        h4_acc(acc, __ldg((const uint2*)&xw[(size_t)s2 * F_OUT + f]));
        h4_acc(acc, __ldg((const uint2*)&xw[(size_t)s3 * F_OUT + f]));
    }
    for (; i < end; i++) {
        const int s = __ldg(&g_csrc[i]);
        h4_acc(acc, __ldg((const uint2*)&xw[(size_t)s * F_OUT + f]));
    }
    const float nd = g_nd[node];
    float4 o;
    o.x = fmaf(acc.x, nd, __ldg(&b2[f + 0]));
    o.y = fmaf(acc.y, nd, __ldg(&b2[f + 1]));
    o.z = fmaf(acc.z, nd, __ldg(&b2[f + 2]));
    o.w = fmaf(acc.w, nd, __ldg(&b2[f + 3]));
    *(float4*)&out[(size_t)node * F_OUT + f] = o;
}

// ---------------- host launch ----------------
extern "C" void kernel_launch(void* const* d_in, const int* in_sizes, int n_in,
                              void* d_out, int out_size) {
    (void)in_sizes; (void)n_in; (void)out_size;
    const float* h   = (const float*)d_in[0];
    const float* W0  = (const float*)d_in[1];
    const float* b0  = (const float*)d_in[2];
    const float* W1  = (const float*)d_in[3];
    const float* b1  = (const float*)d_in[4];
    const float* W2  = (const float*)d_in[5];
    const float* b2  = (const float*)d_in[6];
    const int*   src = (const int*)d_in[7];
    const int*   dst = (const int*)d_in[8];
    float* out = (float*)d_out;

    __half *pHH, *pXW64, *pXW64b, *pXW40;
    cudaGetSymbolAddress((void**)&pHH,    g_hh);
    cudaGetSymbolAddress((void**)&pXW64,  g_xw64);
    cudaGetSymbolAddress((void**)&pXW64b, g_xw64b);
    cudaGetSymbolAddress((void**)&pXW40,  g_xw40);

    static cudaStream_t s2 = []() {
        cudaStream_t s; cudaStreamCreateWithFlags(&s, cudaStreamNonBlocking); return s;
    }();
    auto mkev = []() {
        cudaEvent_t e; cudaEventCreateWithFlags(&e, cudaEventDisableTiming); return e;
    };
    static cudaEvent_t evF0   = mkev();
    static cudaEvent_t evJoin = mkev();

    const int node4Blocks  = (N_NODES / 4 + 255) / 256;
    const int edge4Blocks  = (N_EDGES / 4 + 255) / 256;
    const int cvtBlocks    = (N_NODES * F_IN / 8 + 255) / 256;
    const int gemmBlocks   = (N_NODES + 127) / 128;
    const int gath40Blocks = (N_NODES + 15) / 16;

    // ---- fork immediately ----
    cudaEventRecord(evF0, 0);

    // ---- side stream: h->fp16, zero degs, src-degree, gemm0 (ns inline) ----
    cudaStreamWaitEvent(s2, evF0, 0);
    k_cvt_h<<<cvtBlocks, 256, 0, s2>>>(h);
    k_zero_degs<<<node4Blocks, 256, 0, s2>>>();
    k_deg_src<<<edge4Blocks, 256, 0, s2>>>(src);
    k_gemm0<<<gemmBlocks, 256, 0, s2>>>(pHH, W0, pXW64);
    cudaEventRecord(evJoin, s2);

    // ---- main: zero degd, dst histogram (+pos), scan, finalize, fill ----
    k_zero_degd<<<node4Blocks, 256>>>();
    k_deg_dst_pos<<<edge4Blocks, 256>>>(dst);
    k_scan_block<<<SCAN_NB, SCAN_T>>>();
    k_finalize<<<SCAN_NB, SCAN_T>>>();
    k_fill<<<edge4Blocks, 256>>>(src, dst);

    // ---- join, then fused back chain: 3 kernels ----
    cudaStreamWaitEvent(0, evJoin, 0);
    k_fused<F_HID><<<gemmBlocks, 256>>>(pXW64, W1, pXW64b, b0);
    k_fused<F_OUT><<<gemmBlocks, 256>>>(pXW64b, W2, pXW40, b1);
    k_gather40<<<gath40Blocks, 256>>>(pXW40, out, b2);
}

// round 15
// speedup vs baseline: 1.1886x; 1.1886x over previous
#include <cuda_runtime.h>
#include <cuda_fp16.h>
#include <mma.h>
#include <cstdint>

using namespace nvcuda;

#define N_NODES 100000
#define N_EDGES 1600000
#define F_IN    128
#define F_HID   64
#define F_OUT   40

#define SCAN_T  1024
#define SCAN_NB ((N_NODES + SCAN_T - 1) / SCAN_T)   // 98

// ---------------- scratch (static device globals; no allocation) ----------------
__device__ int    g_degs_i[N_NODES];
__device__ int    g_degd_i[N_NODES];
__device__ float  g_nd[N_NODES];
__device__ int    g_incl[N_NODES];
__device__ int    g_rowoff[N_NODES + 1];
__device__ int    g_partial[SCAN_NB];
__device__ int    g_pos[N_EDGES];
__device__ int    g_csrc[N_EDGES];
__device__ __half g_hh  [(size_t)N_NODES * F_IN];
__device__ __half g_xw64[(size_t)N_NODES * F_HID];
__device__ __half g_xw40[(size_t)N_NODES * F_OUT];
__device__ __half g_agg [(size_t)N_NODES * F_HID];

// inline ns from src-degree (replaces the k_ns kernel)
__device__ __forceinline__ float ns_of(int node) {
    return rsqrtf(fmaxf((float)g_degs_i[node], 1.0f));
}

// ---------------- h -> fp16 streaming convert ----------------
__global__ void k_cvt_h(const float* __restrict__ h) {
    int i = blockIdx.x * blockDim.x + threadIdx.x;
    if (i < N_NODES * F_IN / 8) {
        const float4 a = __ldg(&((const float4*)h)[2 * i + 0]);
        const float4 b = __ldg(&((const float4*)h)[2 * i + 1]);
        union { uint4 u; __half2 x[4]; } o;
        o.x[0] = __floats2half2_rn(a.x, a.y);
        o.x[1] = __floats2half2_rn(a.z, a.w);
        o.x[2] = __floats2half2_rn(b.x, b.y);
        o.x[3] = __floats2half2_rn(b.z, b.w);
        ((uint4*)g_hh)[i] = o.u;
    }
}

// ---------------- per-stream degree zeroing ----------------
__global__ void k_zero_degd() {
    int i = blockIdx.x * blockDim.x + threadIdx.x;
    if (i < N_NODES / 4) ((int4*)g_degd_i)[i] = make_int4(0, 0, 0, 0);
}
__global__ void k_zero_degs() {
    int i = blockIdx.x * blockDim.x + threadIdx.x;
    if (i < N_NODES / 4) ((int4*)g_degs_i)[i] = make_int4(0, 0, 0, 0);
}

// ---------------- dst histogram + per-edge position capture ----------------
__global__ void k_deg_dst_pos(const int* __restrict__ dst) {
    int i = blockIdx.x * blockDim.x + threadIdx.x;
    if (i < N_EDGES / 4) {
        const int4 d = __ldg(&((const int4*)dst)[i]);
        int4 p;
        p.x = atomicAdd(&g_degd_i[d.x], 1);
        p.y = atomicAdd(&g_degd_i[d.y], 1);
        p.z = atomicAdd(&g_degd_i[d.z], 1);
        p.w = atomicAdd(&g_degd_i[d.w], 1);
        ((int4*)g_pos)[i] = p;
    }
}

__global__ void k_deg_src(const int* __restrict__ src) {
    int i = blockIdx.x * blockDim.x + threadIdx.x;
    if (i < N_EDGES / 4) {
        const int4 s = __ldg(&((const int4*)src)[i]);
        atomicAdd(&g_degs_i[s.x], 1);
        atomicAdd(&g_degs_i[s.y], 1);
        atomicAdd(&g_degs_i[s.z], 1);
        atomicAdd(&g_degs_i[s.w], 1);
    }
}

// ---------------- CSR build ----------------
__global__ __launch_bounds__(SCAN_T) void k_scan_block() {
    __shared__ int ws[32];
    int g = blockIdx.x * SCAN_T + threadIdx.x;
    int lane = threadIdx.x & 31, wid = threadIdx.x >> 5;
    int x = (g < N_NODES) ? g_degd_i[g] : 0;
#pragma unroll
    for (int o = 1; o < 32; o <<= 1) {
        int y = __shfl_up_sync(0xFFFFFFFFu, x, o);
        if (lane >= o) x += y;
    }
    if (lane == 31) ws[wid] = x;
    __syncthreads();
    if (wid == 0) {
        int y = ws[lane];
#pragma unroll
        for (int o = 1; o < 32; o <<= 1) {
            int z = __shfl_up_sync(0xFFFFFFFFu, y, o);
            if (lane >= o) y += z;
        }
        ws[lane] = y;
    }
    __syncthreads();
    int incl = x + (wid > 0 ? ws[wid - 1] : 0);
    if (g < N_NODES) g_incl[g] = incl;
    if (threadIdx.x == SCAN_T - 1) g_partial[blockIdx.x] = incl;
}

__global__ __launch_bounds__(SCAN_T) void k_finalize() {
    __shared__ int ws[32];
    __shared__ int s_off;
    const int tid = threadIdx.x;
    const int lane = tid & 31, w = tid >> 5;

    int v = 0;
    if (tid < SCAN_NB && tid < blockIdx.x) v = g_partial[tid];
#pragma unroll
    for (int o = 16; o > 0; o >>= 1) v += __shfl_down_sync(0xFFFFFFFFu, v, o);
    if (tid < 128 && lane == 0) ws[w] = v;
    __syncthreads();
    if (tid == 0) s_off = ws[0] + ws[1] + ws[2] + ws[3];
    __syncthreads();
    const int off = s_off;

    int g = blockIdx.x * SCAN_T + tid;
    if (g < N_NODES) {
        int dd   = g_degd_i[g];
        int incl = g_incl[g] + off;
        g_rowoff[g + 1] = incl;
        if (g == 0) g_rowoff[0] = 0;
        g_nd[g] = rsqrtf(fmaxf((float)dd, 1.0f));
    }
}

__global__ void k_fill(const int* __restrict__ src, const int* __restrict__ dst) {
    int i = blockIdx.x * blockDim.x + threadIdx.x;
    if (i < N_EDGES / 4) {
        const int4 s = __ldg(&((const int4*)src)[i]);
        const int4 d = __ldg(&((const int4*)dst)[i]);
        const int4 p = __ldg(&((const int4*)g_pos)[i]);
        g_csrc[__ldg(&g_rowoff[d.x]) + p.x] = s.x;
        g_csrc[__ldg(&g_rowoff[d.y]) + p.y] = s.y;
        g_csrc[__ldg(&g_rowoff[d.z]) + p.z] = s.z;
        g_csrc[__ldg(&g_rowoff[d.w]) + p.w] = s.w;
    }
}

// ---------------- HMMA GEMM, K-pipelined double buffer: Y = op(X)[fp16] @ W -> fp16 ----------------
// Block tile 128 rows x 64 cols, 8 warps.  PRE: x' = relu(x*nd+b).  SNS: y = acc*ns (inline).
template <int K, int M, bool PRE, bool SNS>
__global__ __launch_bounds__(256) void k_gemm_mma(const __half* __restrict__ X,
                                                  const float* __restrict__ W,
                                                  __half* __restrict__ Y,
                                                  const float* __restrict__ bpre) {
    static constexpr int KC = 64;
    static constexpr int NC = K / KC;
    static constexpr int AL = KC + 8;
    static constexpr int BL = 72;
    static constexpr int A_HALVES = 128 * AL;
    static constexpr int AB_BYTES = 2 * A_HALVES * 2 + K * BL * 2;
    static constexpr int STAGE_BYTES = 8 * 16 * 64 * 4;
    static constexpr int SMEM_BYTES = AB_BYTES > STAGE_BYTES ? AB_BYTES : STAGE_BYTES;

    __shared__ __align__(16) char smem[SMEM_BYTES];
    __half* As0 = (__half*)smem;
    __half* As1 = (__half*)smem + A_HALVES;
    __half* Bs  = (__half*)smem + 2 * A_HALVES;
    float*  Cs  = (float*)smem;

    const int tid  = threadIdx.x;
    const int warp = tid >> 5;
    const int lane = tid & 31;
    const int row0 = blockIdx.x * 128;

    const int ar   = tid >> 1;
    const int ah   = (tid & 1) * 32;
    const int lrow = row0 + ar;
    const bool lok = (lrow < N_NODES);
    float ndv = 0.0f;
    if (PRE) ndv = lok ? g_nd[lrow] : 0.0f;

#pragma unroll
    for (int i = 0; i < K / 16; i++) {
        const int q    = i * 256 + tid;
        const int brow = q >> 4;
        const int bcol = (q & 15) * 4;
        float4 wv = make_float4(0.f, 0.f, 0.f, 0.f);
        if (bcol < M)
            wv = *(const float4*)&W[(size_t)brow * M + bcol];
        union { uint2 u; __half2 h[2]; } p;
        p.h[0] = __floats2half2_rn(wv.x, wv.y);
        p.h[1] = __floats2half2_rn(wv.z, wv.w);
        *(uint2*)&Bs[brow * BL + bcol] = p.u;
    }

    uint4 raw[4] = {{0,0,0,0}, {0,0,0,0}, {0,0,0,0}, {0,0,0,0}};
    if (lok) {
#pragma unroll
        for (int u = 0; u < 4; u++)
            raw[u] = __ldg((const uint4*)&X[(size_t)lrow * K + ah + u * 8]);
    }
    {
        __half* Ad = As0;
#pragma unroll
        for (int u = 0; u < 4; u++) {
            union { uint4 q; __half2 h[4]; } in; in.q = raw[u];
            if (PRE) {
                union { uint4 q; __half2 h[4]; } o;
#pragma unroll
                for (int j = 0; j < 4; j++) {
                    const float2 v = __half22float2(in.h[j]);
                    const int k = ah + u * 8 + 2 * j;
                    o.h[j] = __floats2half2_rn(
                        fmaxf(fmaf(v.x, ndv, __ldg(&bpre[k + 0])), 0.f),
                        fmaxf(fmaf(v.y, ndv, __ldg(&bpre[k + 1])), 0.f));
                }
                *(uint4*)&Ad[ar * AL + ah + u * 8] = o.q;
            } else {
                *(uint4*)&Ad[ar * AL + ah + u * 8] = in.q;
            }
        }
    }
    __syncthreads();

    wmma::fragment<wmma::accumulator, 16, 16, 16, float> cf[4];
#pragma unroll
    for (int n = 0; n < 4; n++) wmma::fill_fragment(cf[n], 0.0f);

#pragma unroll
    for (int c = 0; c < NC; c++) {
        if (c + 1 < NC && lok) {
#pragma unroll
            for (int u = 0; u < 4; u++)
                raw[u] = __ldg((const uint4*)&X[(size_t)lrow * K + (c + 1) * KC + ah + u * 8]);
        }
        const __half* Ac = (c & 1) ? As1 : As0;
#pragma unroll
        for (int kc = 0; kc < KC; kc += 16) {
            wmma::fragment<wmma::matrix_a, 16, 16, 16, __half, wmma::row_major> af;
            wmma::load_matrix_sync(af, &Ac[(warp * 16) * AL + kc], AL);
#pragma unroll
            for (int n = 0; n < 4; n++) {
                wmma::fragment<wmma::matrix_b, 16, 16, 16, __half, wmma::row_major> bf;
                wmma::load_matrix_sync(bf, &Bs[(c * KC + kc) * BL + n * 16], BL);
                wmma::mma_sync(cf[n], af, bf, cf[n]);
            }
        }
        if (c + 1 < NC) {
            __half* Ad = ((c + 1) & 1) ? As1 : As0;
#pragma unroll
            for (int u = 0; u < 4; u++) {
                union { uint4 q; __half2 h[4]; } in; in.q = raw[u];
                if (PRE) {
                    union { uint4 q; __half2 h[4]; } o;
#pragma unroll
                    for (int j = 0; j < 4; j++) {
                        const float2 v = __half22float2(in.h[j]);
                        const int k = (c + 1) * KC + ah + u * 8 + 2 * j;
                        o.h[j] = __floats2half2_rn(
                            fmaxf(fmaf(v.x, ndv, __ldg(&bpre[k + 0])), 0.f),
                            fmaxf(fmaf(v.y, ndv, __ldg(&bpre[k + 1])), 0.f));
                    }
                    *(uint4*)&Ad[ar * AL + ah + u * 8] = o.q;
                } else {
                    *(uint4*)&Ad[ar * AL + ah + u * 8] = in.q;
                }
            }
            __syncthreads();
        }
    }
    __syncthreads();

    float* cwarp = Cs + warp * (16 * 64);
#pragma unroll
    for (int n = 0; n < 4; n++)
        wmma::store_matrix_sync(cwarp + n * 16, cf[n], 64, wmma::mem_row_major);
    __syncwarp();

    for (int q = lane; q < 256; q += 32) {
        const int r  = q >> 4;
        const int qc = (q & 15) * 4;
        const int rr = row0 + warp * 16 + r;
        if (rr < N_NODES && qc < M) {
            const float s = SNS ? ns_of(rr) : 1.0f;
            union { uint2 u; __half2 h[2]; } p;
            p.h[0] = __floats2half2_rn(cwarp[r * 64 + qc + 0] * s, cwarp[r * 64 + qc + 1] * s);
            p.h[1] = __floats2half2_rn(cwarp[r * 64 + qc + 2] * s, cwarp[r * 64 + qc + 3] * s);
            *(uint2*)&Y[(size_t)rr * M + qc] = p.u;
        }
    }
}

// ---------------- CSR gather (fp16 in/out, fp32 accum): 8 thr/node, 16B loads ----------------
__device__ __forceinline__ void h8_acc(float* acc, uint4 raw) {
    union { uint4 u; __half2 h[4]; } p; p.u = raw;
#pragma unroll
    for (int j = 0; j < 4; j++) {
        const float2 v = __half22float2(p.h[j]);
        acc[2 * j + 0] += v.x;
        acc[2 * j + 1] += v.y;
    }
}

__global__ __launch_bounds__(256) void k_gather64(const __half* __restrict__ xw,
                                                  __half* __restrict__ agg) {
    const int node = blockIdx.x * 32 + (threadIdx.x >> 3);
    if (node >= N_NODES) return;
    const int f   = (threadIdx.x & 7) << 3;
    int       i   = g_rowoff[node];
    const int end = g_rowoff[node + 1];
    float acc[8] = {0.f, 0.f, 0.f, 0.f, 0.f, 0.f, 0.f, 0.f};

    for (; i + 3 < end; i += 4) {
        const int s0 = __ldg(&g_csrc[i + 0]);
        const int s1 = __ldg(&g_csrc[i + 1]);
        const int s2 = __ldg(&g_csrc[i + 2]);
        const int s3 = __ldg(&g_csrc[i + 3]);
        const uint4 r0 = __ldg((const uint4*)&xw[(size_t)s0 * 64 + f]);
        const uint4 r1 = __ldg((const uint4*)&xw[(size_t)s1 * 64 + f]);
        const uint4 r2 = __ldg((const uint4*)&xw[(size_t)s2 * 64 + f]);
        const uint4 r3 = __ldg((const uint4*)&xw[(size_t)s3 * 64 + f]);
        h8_acc(acc, r0); h8_acc(acc, r1);
        h8_acc(acc, r2); h8_acc(acc, r3);
    }
    for (; i < end; i++) {
        const int s = __ldg(&g_csrc[i]);
        h8_acc(acc, __ldg((const uint4*)&xw[(size_t)s * 64 + f]));
    }

    union { uint4 u; __half2 h[4]; } o;
    o.h[0] = __floats2half2_rn(acc[0], acc[1]);
    o.h[1] = __floats2half2_rn(acc[2], acc[3]);
    o.h[2] = __floats2half2_rn(acc[4], acc[5]);
    o.h[3] = __floats2half2_rn(acc[6], acc[7]);
    *(uint4*)&agg[(size_t)node * 64 + f] = o.u;
}

// ---------------- 40-wide fp16 gather with fused final epilogue (fp32 output) ----------------
__device__ __forceinline__ void h4_acc(float4& acc, uint2 raw) {
    union { uint2 u; __half2 h[2]; } p; p.u = raw;
    const float2 a = __half22float2(p.h[0]);
    const float2 b = __half22float2(p.h[1]);
    acc.x += a.x; acc.y += a.y; acc.z += b.x; acc.w += b.y;
}

__global__ __launch_bounds__(256) void k_gather40(const __half* __restrict__ xw,
                                                  float* __restrict__ out,
                                                  const float* __restrict__ b2) {
    const int node = blockIdx.x * 16 + (threadIdx.x >> 4);
    if (node >= N_NODES) return;
    const int f = (threadIdx.x & 15) << 2;
    if (f >= F_OUT) return;
    int       i   = g_rowoff[node];
    const int end = g_rowoff[node + 1];
    float4 acc = make_float4(0.f, 0.f, 0.f, 0.f);
    for (; i + 3 < end; i += 4) {
        const int s0 = __ldg(&g_csrc[i + 0]);
        const int s1 = __ldg(&g_csrc[i + 1]);
        const int s2 = __ldg(&g_csrc[i + 2]);
        const int s3 = __ldg(&g_csrc[i + 3]);
        h4_acc(acc, __ldg((const uint2*)&xw[(size_t)s0 * F_OUT + f]));
        h4_acc(acc, __ldg((const uint2*)&xw[(size_t)s1 * F_OUT + f]));
        h4_acc(acc, __ldg((const uint2*)&xw[(size_t)s2 * F_OUT + f]));
        h4_acc(acc, __ldg((const uint2*)&xw[(size_t)s3 * F_OUT + f]));
    }
    for (; i < end; i++) {
        const int s = __ldg(&g_csrc[i]);
        h4_acc(acc, __ldg((const uint2*)&xw[(size_t)s * F_OUT + f]));
    }
    const float nd = g_nd[node];
    float4 o;
    o.x = fmaf(acc.x, nd, __ldg(&b2[f + 0]));
    o.y = fmaf(acc.y, nd, __ldg(&b2[f + 1]));
    o.z = fmaf(acc.z, nd, __ldg(&b2[f + 2]));
    o.w = fmaf(acc.w, nd, __ldg(&b2[f + 3]));
    *(float4*)&out[(size_t)node * F_OUT + f] = o;
}

// ---------------- host launch ----------------
extern "C" void kernel_launch(void* const* d_in, const int* in_sizes, int n_in,
                              void* d_out, int out_size) {
    (void)in_sizes; (void)n_in; (void)out_size;
    const float* h   = (const float*)d_in[0];
    const float* W0  = (const float*)d_in[1];
    const float* b0  = (const float*)d_in[2];
    const float* W1  = (const float*)d_in[3];
    const float* b1  = (const float*)d_in[4];
    const float* W2  = (const float*)d_in[5];
    const float* b2  = (const float*)d_in[6];
    const int*   src = (const int*)d_in[7];
    const int*   dst = (const int*)d_in[8];
    float* out = (float*)d_out;

    __half *pHH, *pXW64, *pXW40, *pAgg;
    cudaGetSymbolAddress((void**)&pHH,   g_hh);
    cudaGetSymbolAddress((void**)&pXW64, g_xw64);
    cudaGetSymbolAddress((void**)&pXW40, g_xw40);
    cudaGetSymbolAddress((void**)&pAgg,  g_agg);

    static cudaStream_t s2 = []() {
        cudaStream_t s; cudaStreamCreateWithFlags(&s, cudaStreamNonBlocking); return s;
    }();
    auto mkev = []() {
        cudaEvent_t e; cudaEventCreateWithFlags(&e, cudaEventDisableTiming); return e;
    };
    static cudaEvent_t evF0   = mkev();
    static cudaEvent_t evJoin = mkev();

    const int node4Blocks  = (N_NODES / 4 + 255) / 256;
    const int edge4Blocks  = (N_EDGES / 4 + 255) / 256;
    const int cvtBlocks    = (N_NODES * F_IN / 8 + 255) / 256;
    const int gemmBlocks   = (N_NODES + 127) / 128;
    const int gath64Blocks = (N_NODES + 31) / 32;
    const int gath40Blocks = (N_NODES + 15) / 16;

    // ---- fork immediately; each stream zeroes its own degree array ----
    cudaEventRecord(evF0, 0);

    // ---- side stream: h->fp16, zero degs, src-degree, gemm0 (ns inline) ----
    cudaStreamWaitEvent(s2, evF0, 0);
    k_cvt_h<<<cvtBlocks, 256, 0, s2>>>(h);
    k_zero_degs<<<node4Blocks, 256, 0, s2>>>();
    k_deg_src<<<edge4Blocks, 256, 0, s2>>>(src);
    k_gemm_mma<F_IN, F_HID, false, true><<<gemmBlocks, 256, 0, s2>>>(pHH, W0, pXW64, b0);
    cudaEventRecord(evJoin, s2);

    // ---- main: zero degd, dst histogram (+pos), scan, finalize, fill ----
    k_zero_degd<<<node4Blocks, 256>>>();
    k_deg_dst_pos<<<edge4Blocks, 256>>>(dst);
    k_scan_block<<<SCAN_NB, SCAN_T>>>();
    k_finalize<<<SCAN_NB, SCAN_T>>>();
    k_fill<<<edge4Blocks, 256>>>(src, dst);

    // ---- join, then the serial back chain (R13 topology) ----
    cudaStreamWaitEvent(0, evJoin, 0);
    k_gather64<<<gath64Blocks, 256>>>(pXW64, pAgg);

    k_gemm_mma<F_HID, F_HID, true, true><<<gemmBlocks, 256>>>(pAgg, W1, pXW64, b0);
    k_gather64<<<gath64Blocks, 256>>>(pXW64, pAgg);

    k_gemm_mma<F_HID, F_OUT, true, true><<<gemmBlocks, 256>>>(pAgg, W2, pXW40, b1);
    k_gather40<<<gath40Blocks, 256>>>(pXW40, out, b2);
}

// round 16
// speedup vs baseline: 1.2213x; 1.0275x over previous
#include <cuda_runtime.h>
#include <cuda_fp16.h>
#include <mma.h>
#include <cstdint>

using namespace nvcuda;

#define N_NODES 100000
#define N_EDGES 1600000
#define F_IN    128
#define F_HID   64
#define F_OUT   40

#define SCAN_T  1024
#define SCAN_NB ((N_NODES + SCAN_T - 1) / SCAN_T)   // 98

// ---------------- scratch (static device globals; no allocation) ----------------
__device__ int            g_degs_i[N_NODES];
__device__ int            g_degd_i[N_NODES];
__device__ float          g_nd[N_NODES];
__device__ int            g_incl[N_NODES];
__device__ int            g_rowoff[N_NODES + 1];
__device__ int            g_partial[SCAN_NB];
__device__ unsigned short g_pos[N_EDGES];            // per-edge slot (max degree << 65536)
__device__ int            g_csrc[N_EDGES];
__device__ __half         g_hh  [(size_t)N_NODES * F_IN];
__device__ __half         g_xw64[(size_t)N_NODES * F_HID];
__device__ __half         g_xw40[(size_t)N_NODES * F_OUT];
__device__ __half         g_agg [(size_t)N_NODES * F_HID];

// inline ns from src-degree
__device__ __forceinline__ float ns_of(int node) {
    return rsqrtf(fmaxf((float)g_degs_i[node], 1.0f));
}

// ---------------- h -> fp16 streaming convert (+ zero degs histogram, folded) ----------------
__global__ void k_cvt_h(const float* __restrict__ h) {
    int i = blockIdx.x * blockDim.x + threadIdx.x;
    if (i < N_NODES / 4)
        ((int4*)g_degs_i)[i] = make_int4(0, 0, 0, 0);
    if (i < N_NODES * F_IN / 8) {
        const float4 a = __ldg(&((const float4*)h)[2 * i + 0]);
        const float4 b = __ldg(&((const float4*)h)[2 * i + 1]);
        union { uint4 u; __half2 x[4]; } o;
        o.x[0] = __floats2half2_rn(a.x, a.y);
        o.x[1] = __floats2half2_rn(a.z, a.w);
        o.x[2] = __floats2half2_rn(b.x, b.y);
        o.x[3] = __floats2half2_rn(b.z, b.w);
        ((uint4*)g_hh)[i] = o.u;
    }
}

__global__ void k_zero_degd() {
    int i = blockIdx.x * blockDim.x + threadIdx.x;
    if (i < N_NODES / 4) ((int4*)g_degd_i)[i] = make_int4(0, 0, 0, 0);
}

// ---------------- dst histogram + per-edge position capture (ushort) ----------------
__global__ void k_deg_dst_pos(const int* __restrict__ dst) {
    int i = blockIdx.x * blockDim.x + threadIdx.x;
    if (i < N_EDGES / 4) {
        const int4 d = __ldg(&((const int4*)dst)[i]);
        ushort4 p;
        p.x = (unsigned short)atomicAdd(&g_degd_i[d.x], 1);
        p.y = (unsigned short)atomicAdd(&g_degd_i[d.y], 1);
        p.z = (unsigned short)atomicAdd(&g_degd_i[d.z], 1);
        p.w = (unsigned short)atomicAdd(&g_degd_i[d.w], 1);
        ((ushort4*)g_pos)[i] = p;
    }
}

__global__ void k_deg_src(const int* __restrict__ src) {
    int i = blockIdx.x * blockDim.x + threadIdx.x;
    if (i < N_EDGES / 4) {
        const int4 s = __ldg(&((const int4*)src)[i]);
        atomicAdd(&g_degs_i[s.x], 1);
        atomicAdd(&g_degs_i[s.y], 1);
        atomicAdd(&g_degs_i[s.z], 1);
        atomicAdd(&g_degs_i[s.w], 1);
    }
}

// ---------------- CSR build ----------------
__global__ __launch_bounds__(SCAN_T) void k_scan_block() {
    __shared__ int ws[32];
    int g = blockIdx.x * SCAN_T + threadIdx.x;
    int lane = threadIdx.x & 31, wid = threadIdx.x >> 5;
    int x = (g < N_NODES) ? g_degd_i[g] : 0;
#pragma unroll
    for (int o = 1; o < 32; o <<= 1) {
        int y = __shfl_up_sync(0xFFFFFFFFu, x, o);
        if (lane >= o) x += y;
    }
    if (lane == 31) ws[wid] = x;
    __syncthreads();
    if (wid == 0) {
        int y = ws[lane];
#pragma unroll
        for (int o = 1; o < 32; o <<= 1) {
            int z = __shfl_up_sync(0xFFFFFFFFu, y, o);
            if (lane >= o) y += z;
        }
        ws[lane] = y;
    }
    __syncthreads();
    int incl = x + (wid > 0 ? ws[wid - 1] : 0);
    if (g < N_NODES) g_incl[g] = incl;
    if (threadIdx.x == SCAN_T - 1) g_partial[blockIdx.x] = incl;
}

__global__ __launch_bounds__(SCAN_T) void k_finalize() {
    __shared__ int ws[32];
    __shared__ int s_off;
    const int tid = threadIdx.x;
    const int lane = tid & 31, w = tid >> 5;

    int v = 0;
    if (tid < SCAN_NB && tid < blockIdx.x) v = g_partial[tid];
#pragma unroll
    for (int o = 16; o > 0; o >>= 1) v += __shfl_down_sync(0xFFFFFFFFu, v, o);
    if (tid < 128 && lane == 0) ws[w] = v;
    __syncthreads();
    if (tid == 0) s_off = ws[0] + ws[1] + ws[2] + ws[3];
    __syncthreads();
    const int off = s_off;

    int g = blockIdx.x * SCAN_T + tid;
    if (g < N_NODES) {
        int dd   = g_degd_i[g];
        int incl = g_incl[g] + off;
        g_rowoff[g + 1] = incl;
        if (g == 0) g_rowoff[0] = 0;
        g_nd[g] = rsqrtf(fmaxf((float)dd, 1.0f));
    }
}

__global__ void k_fill(const int* __restrict__ src, const int* __restrict__ dst) {
    int i = blockIdx.x * blockDim.x + threadIdx.x;
    if (i < N_EDGES / 4) {
        const int4   s = __ldg(&((const int4*)src)[i]);
        const int4   d = __ldg(&((const int4*)dst)[i]);
        const ushort4 p = __ldg(&((const ushort4*)g_pos)[i]);
        g_csrc[__ldg(&g_rowoff[d.x]) + p.x] = s.x;
        g_csrc[__ldg(&g_rowoff[d.y]) + p.y] = s.y;
        g_csrc[__ldg(&g_rowoff[d.z]) + p.z] = s.z;
        g_csrc[__ldg(&g_rowoff[d.w]) + p.w] = s.w;
    }
}

// ---------------- HMMA GEMM, K-pipelined double buffer: Y = op(X)[fp16] @ W -> fp16 ----------------
template <int K, int M, bool PRE, bool SNS>
__global__ __launch_bounds__(256) void k_gemm_mma(const __half* __restrict__ X,
                                                  const float* __restrict__ W,
                                                  __half* __restrict__ Y,
                                                  const float* __restrict__ bpre) {
    static constexpr int KC = 64;
    static constexpr int NC = K / KC;
    static constexpr int AL = KC + 8;
    static constexpr int BL = 72;
    static constexpr int A_HALVES = 128 * AL;
    static constexpr int AB_BYTES = 2 * A_HALVES * 2 + K * BL * 2;
    static constexpr int STAGE_BYTES = 8 * 16 * 64 * 4;
    static constexpr int SMEM_BYTES = AB_BYTES > STAGE_BYTES ? AB_BYTES : STAGE_BYTES;

    __shared__ __align__(16) char smem[SMEM_BYTES];
    __half* As0 = (__half*)smem;
    __half* As1 = (__half*)smem + A_HALVES;
    __half* Bs  = (__half*)smem + 2 * A_HALVES;
    float*  Cs  = (float*)smem;

    const int tid  = threadIdx.x;
    const int warp = tid >> 5;
    const int lane = tid & 31;
    const int row0 = blockIdx.x * 128;

    const int ar   = tid >> 1;
    const int ah   = (tid & 1) * 32;
    const int lrow = row0 + ar;
    const bool lok = (lrow < N_NODES);
    float ndv = 0.0f;
    if (PRE) ndv = lok ? g_nd[lrow] : 0.0f;

#pragma unroll
    for (int i = 0; i < K / 16; i++) {
        const int q    = i * 256 + tid;
        const int brow = q >> 4;
        const int bcol = (q & 15) * 4;
        float4 wv = make_float4(0.f, 0.f, 0.f, 0.f);
        if (bcol < M)
            wv = *(const float4*)&W[(size_t)brow * M + bcol];
        union { uint2 u; __half2 h[2]; } p;
        p.h[0] = __floats2half2_rn(wv.x, wv.y);
        p.h[1] = __floats2half2_rn(wv.z, wv.w);
        *(uint2*)&Bs[brow * BL + bcol] = p.u;
    }

    uint4 raw[4] = {{0,0,0,0}, {0,0,0,0}, {0,0,0,0}, {0,0,0,0}};
    if (lok) {
#pragma unroll
        for (int u = 0; u < 4; u++)
            raw[u] = __ldg((const uint4*)&X[(size_t)lrow * K + ah + u * 8]);
    }
    {
        __half* Ad = As0;
#pragma unroll
        for (int u = 0; u < 4; u++) {
            union { uint4 q; __half2 h[4]; } in; in.q = raw[u];
            if (PRE) {
                union { uint4 q; __half2 h[4]; } o;
#pragma unroll
                for (int j = 0; j < 4; j++) {
                    const float2 v = __half22float2(in.h[j]);
                    const int k = ah + u * 8 + 2 * j;
                    o.h[j] = __floats2half2_rn(
                        fmaxf(fmaf(v.x, ndv, __ldg(&bpre[k + 0])), 0.f),
                        fmaxf(fmaf(v.y, ndv, __ldg(&bpre[k + 1])), 0.f));
                }
                *(uint4*)&Ad[ar * AL + ah + u * 8] = o.q;
            } else {
                *(uint4*)&Ad[ar * AL + ah + u * 8] = in.q;
            }
        }
    }
    __syncthreads();

    wmma::fragment<wmma::accumulator, 16, 16, 16, float> cf[4];
#pragma unroll
    for (int n = 0; n < 4; n++) wmma::fill_fragment(cf[n], 0.0f);

#pragma unroll
    for (int c = 0; c < NC; c++) {
        if (c + 1 < NC && lok) {
#pragma unroll
            for (int u = 0; u < 4; u++)
                raw[u] = __ldg((const uint4*)&X[(size_t)lrow * K + (c + 1) * KC + ah + u * 8]);
        }
        const __half* Ac = (c & 1) ? As1 : As0;
#pragma unroll
        for (int kc = 0; kc < KC; kc += 16) {
            wmma::fragment<wmma::matrix_a, 16, 16, 16, __half, wmma::row_major> af;
            wmma::load_matrix_sync(af, &Ac[(warp * 16) * AL + kc], AL);
#pragma unroll
            for (int n = 0; n < 4; n++) {
                wmma::fragment<wmma::matrix_b, 16, 16, 16, __half, wmma::row_major> bf;
                wmma::load_matrix_sync(bf, &Bs[(c * KC + kc) * BL + n * 16], BL);
                wmma::mma_sync(cf[n], af, bf, cf[n]);
            }
        }
        if (c + 1 < NC) {
            __half* Ad = ((c + 1) & 1) ? As1 : As0;
#pragma unroll
            for (int u = 0; u < 4; u++) {
                union { uint4 q; __half2 h[4]; } in; in.q = raw[u];
                if (PRE) {
                    union { uint4 q; __half2 h[4]; } o;
#pragma unroll
                    for (int j = 0; j < 4; j++) {
                        const float2 v = __half22float2(in.h[j]);
                        const int k = (c + 1) * KC + ah + u * 8 + 2 * j;
                        o.h[j] = __floats2half2_rn(
                            fmaxf(fmaf(v.x, ndv, __ldg(&bpre[k + 0])), 0.f),
                            fmaxf(fmaf(v.y, ndv, __ldg(&bpre[k + 1])), 0.f));
                    }
                    *(uint4*)&Ad[ar * AL + ah + u * 8] = o.q;
                } else {
                    *(uint4*)&Ad[ar * AL + ah + u * 8] = in.q;
                }
            }
            __syncthreads();
        }
    }
    __syncthreads();

    float* cwarp = Cs + warp * (16 * 64);
#pragma unroll
    for (int n = 0; n < 4; n++)
        wmma::store_matrix_sync(cwarp + n * 16, cf[n], 64, wmma::mem_row_major);
    __syncwarp();

    for (int q = lane; q < 256; q += 32) {
        const int r  = q >> 4;
        const int qc = (q & 15) * 4;
        const int rr = row0 + warp * 16 + r;
        if (rr < N_NODES && qc < M) {
            const float s = SNS ? ns_of(rr) : 1.0f;
            union { uint2 u; __half2 h[2]; } p;
            p.h[0] = __floats2half2_rn(cwarp[r * 64 + qc + 0] * s, cwarp[r * 64 + qc + 1] * s);
            p.h[1] = __floats2half2_rn(cwarp[r * 64 + qc + 2] * s, cwarp[r * 64 + qc + 3] * s);
            *(uint2*)&Y[(size_t)rr * M + qc] = p.u;
        }
    }
}

// ---------------- CSR gather (fp16 in/out, fp32 accum): 8 thr/node, 16B loads ----------------
__device__ __forceinline__ void h8_acc(float* acc, uint4 raw) {
    union { uint4 u; __half2 h[4]; } p; p.u = raw;
#pragma unroll
    for (int j = 0; j < 4; j++) {
        const float2 v = __half22float2(p.h[j]);
        acc[2 * j + 0] += v.x;
        acc[2 * j + 1] += v.y;
    }
}

__global__ __launch_bounds__(256) void k_gather64(const __half* __restrict__ xw,
                                                  __half* __restrict__ agg) {
    const int node = blockIdx.x * 32 + (threadIdx.x >> 3);
    if (node >= N_NODES) return;
    const int f   = (threadIdx.x & 7) << 3;
    int       i   = g_rowoff[node];
    const int end = g_rowoff[node + 1];
    float acc[8] = {0.f, 0.f, 0.f, 0.f, 0.f, 0.f, 0.f, 0.f};

    for (; i + 3 < end; i += 4) {
        const int s0 = __ldg(&g_csrc[i + 0]);
        const int s1 = __ldg(&g_csrc[i + 1]);
        const int s2 = __ldg(&g_csrc[i + 2]);
        const int s3 = __ldg(&g_csrc[i + 3]);
        const uint4 r0 = __ldg((const uint4*)&xw[(size_t)s0 * 64 + f]);
        const uint4 r1 = __ldg((const uint4*)&xw[(size_t)s1 * 64 + f]);
        const uint4 r2 = __ldg((const uint4*)&xw[(size_t)s2 * 64 + f]);
        const uint4 r3 = __ldg((const uint4*)&xw[(size_t)s3 * 64 + f]);
        h8_acc(acc, r0); h8_acc(acc, r1);
        h8_acc(acc, r2); h8_acc(acc, r3);
    }
    for (; i < end; i++) {
        const int s = __ldg(&g_csrc[i]);
        h8_acc(acc, __ldg((const uint4*)&xw[(size_t)s * 64 + f]));
    }

    union { uint4 u; __half2 h[4]; } o;
    o.h[0] = __floats2half2_rn(acc[0], acc[1]);
    o.h[1] = __floats2half2_rn(acc[2], acc[3]);
    o.h[2] = __floats2half2_rn(acc[4], acc[5]);
    o.h[3] = __floats2half2_rn(acc[6], acc[7]);
    *(uint4*)&agg[(size_t)node * 64 + f] = o.u;
}

// ---------------- 40-wide gather, 10 threads/node (all lanes active) ----------------
__device__ __forceinline__ void h4_acc(float4& acc, uint2 raw) {
    union { uint2 u; __half2 h[2]; } p; p.u = raw;
    const float2 a = __half22float2(p.h[0]);
    const float2 b = __half22float2(p.h[1]);
    acc.x += a.x; acc.y += a.y; acc.z += b.x; acc.w += b.y;
}

__global__ __launch_bounds__(256) void k_gather40(const __half* __restrict__ xw,
                                                  float* __restrict__ out,
                                                  const float* __restrict__ b2) {
    const int idx  = blockIdx.x * 256 + threadIdx.x;
    const int node = idx / 10;
    if (node >= N_NODES) return;
    const int f    = (idx - node * 10) * 4;     // 0,4,...,36
    int       i    = g_rowoff[node];
    const int end  = g_rowoff[node + 1];
    float4 acc = make_float4(0.f, 0.f, 0.f, 0.f);
    for (; i + 3 < end; i += 4) {
        const int s0 = __ldg(&g_csrc[i + 0]);
        const int s1 = __ldg(&g_csrc[i + 1]);
        const int s2 = __ldg(&g_csrc[i + 2]);
        const int s3 = __ldg(&g_csrc[i + 3]);
        h4_acc(acc, __ldg((const uint2*)&xw[(size_t)s0 * F_OUT + f]));
        h4_acc(acc, __ldg((const uint2*)&xw[(size_t)s1 * F_OUT + f]));
        h4_acc(acc, __ldg((const uint2*)&xw[(size_t)s2 * F_OUT + f]));
        h4_acc(acc, __ldg((const uint2*)&xw[(size_t)s3 * F_OUT + f]));
    }
    for (; i < end; i++) {
        const int s = __ldg(&g_csrc[i]);
        h4_acc(acc, __ldg((const uint2*)&xw[(size_t)s * F_OUT + f]));
    }
    const float nd = g_nd[node];
    float4 o;
    o.x = fmaf(acc.x, nd, __ldg(&b2[f + 0]));
    o.y = fmaf(acc.y, nd, __ldg(&b2[f + 1]));
    o.z = fmaf(acc.z, nd, __ldg(&b2[f + 2]));
    o.w = fmaf(acc.w, nd, __ldg(&b2[f + 3]));
    *(float4*)&out[(size_t)node * F_OUT + f] = o;
}

// ---------------- host launch ----------------
extern "C" void kernel_launch(void* const* d_in, const int* in_sizes, int n_in,
                              void* d_out, int out_size) {
    (void)in_sizes; (void)n_in; (void)out_size;
    const float* h   = (const float*)d_in[0];
    const float* W0  = (const float*)d_in[1];
    const float* b0  = (const float*)d_in[2];
    const float* W1  = (const float*)d_in[3];
    const float* b1  = (const float*)d_in[4];
    const float* W2  = (const float*)d_in[5];
    const float* b2  = (const float*)d_in[6];
    const int*   src = (const int*)d_in[7];
    const int*   dst = (const int*)d_in[8];
    float* out = (float*)d_out;

    __half *pHH, *pXW64, *pXW40, *pAgg;
    cudaGetSymbolAddress((void**)&pHH,   g_hh);
    cudaGetSymbolAddress((void**)&pXW64, g_xw64);
    cudaGetSymbolAddress((void**)&pXW40, g_xw40);
    cudaGetSymbolAddress((void**)&pAgg,  g_agg);

    static cudaStream_t s2 = []() {
        cudaStream_t s; cudaStreamCreateWithFlags(&s, cudaStreamNonBlocking); return s;
    }();
    auto mkev = []() {
        cudaEvent_t e; cudaEventCreateWithFlags(&e, cudaEventDisableTiming); return e;
    };
    static cudaEvent_t evF0   = mkev();
    static cudaEvent_t evJoin = mkev();

    const int node4Blocks  = (N_NODES / 4 + 255) / 256;
    const int edge4Blocks  = (N_EDGES / 4 + 255) / 256;
    const int cvtBlocks    = (N_NODES * F_IN / 8 + 255) / 256;
    const int gemmBlocks   = (N_NODES + 127) / 128;
    const int gath64Blocks = (N_NODES + 31) / 32;
    const int gath40Blocks = (N_NODES * 10 + 255) / 256;

    // ---- fork immediately ----
    cudaEventRecord(evF0, 0);

    // ---- side stream: h->fp16 (+zero degs), src-degree, gemm0 (ns inline) ----
    cudaStreamWaitEvent(s2, evF0, 0);
    k_cvt_h<<<cvtBlocks, 256, 0, s2>>>(h);
    k_deg_src<<<edge4Blocks, 256, 0, s2>>>(src);
    k_gemm_mma<F_IN, F_HID, false, true><<<gemmBlocks, 256, 0, s2>>>(pHH, W0, pXW64, b0);
    cudaEventRecord(evJoin, s2);

    // ---- main: zero degd, dst histogram (+ushort pos), scan, finalize, fill ----
    k_zero_degd<<<node4Blocks, 256>>>();
    k_deg_dst_pos<<<edge4Blocks, 256>>>(dst);
    k_scan_block<<<SCAN_NB, SCAN_T>>>();
    k_finalize<<<SCAN_NB, SCAN_T>>>();
    k_fill<<<edge4Blocks, 256>>>(src, dst);

    // ---- join, then the serial back chain ----
    cudaStreamWaitEvent(0, evJoin, 0);
    k_gather64<<<gath64Blocks, 256>>>(pXW64, pAgg);

    k_gemm_mma<F_HID, F_HID, true, true><<<gemmBlocks, 256>>>(pAgg, W1, pXW64, b0);
    k_gather64<<<gath64Blocks, 256>>>(pXW64, pAgg);

    k_gemm_mma<F_HID, F_OUT, true, true><<<gemmBlocks, 256>>>(pAgg, W2, pXW40, b1);
    k_gather40<<<gath40Blocks, 256>>>(pXW40, out, b2);
}